// round 12
// baseline (speedup 1.0000x reference)
#include <cuda_runtime.h>
#include <math.h>

#define BATCH 512
#define HO 31
#define WO 31
#define HW 64
#define PLANE (HO * WO)          // 961
#define OUTB (12 * PLANE)        // 11532 floats per batch

// Per-patch closed-form invariants of the quantum circuit:
//   S2 = sum p_i^2 ; D2 = signed sum (row sign (+,-,+,-), col sign (+,-,-,+))
//   dP = sum over pairs (i, i^12): rows 0<->3 and 1<->2, same column
// Output plane 3k+c = cA*D2/S2 + cB*dP/S2 (coefs from U3 of qubit 0 only).
//
// Block = one 8-row patch band of one image (grid 4x512 = 2048 blocks):
//   stage 18 input rows (LDG.128) -> 248 patches from smem -> per plane the
//   band's 248 outputs are CONTIGUOUS -> aligned STG.128 (4x fewer stores).

__global__ __launch_bounds__(256) void qconv_kernel(const float* __restrict__ x,
                                                    const float* __restrict__ w,
                                                    float* __restrict__ out) {
    __shared__ __align__(16) float img[18 * HW];    // 4.6 KB input band
    __shared__ __align__(16) float2 res[248];       // (Dl, dd) per patch
    __shared__ float cA[12], cB[12];

    const int tid = threadIdx.x;
    const int q = blockIdx.x;                       // band 0..3 (8,8,8,7 rows)
    const int b = blockIdx.y;
    const int rows_p = (q < 3) ? 8 : 7;             // patch rows in this band
    const int cnt = rows_p * WO;                    // 248 or 217
    const int irows = 2 * rows_p + 2;               // 18 or 16 input rows

    if (tid < 4) {
        const int k = tid;
        float th = w[k * 12 + 0], ph = w[k * 12 + 1], om = w[k * 12 + 2];
        float st, ct, spo, cpo, smp, cmp, sp, cp, som, com_;
        sincosf(th, &st, &ct);
        sincosf(ph, &sp, &cp);
        sincosf(ph + om, &spo, &cpo);
        sincosf(om - ph, &smp, &cmp);
        sincosf(om, &som, &com_);
        float c2 = 0.5f * (1.0f + ct);
        float s2 = 0.5f * (1.0f - ct);
        cA[3 * k + 0] = st * cp;                        // ex
        cB[3 * k + 0] = 2.0f * (c2 * cpo - s2 * cmp);
        cA[3 * k + 1] = st * sp;                        // ey
        cB[3 * k + 1] = 2.0f * (c2 * spo + s2 * smp);
        cA[3 * k + 2] = ct;                             // ez
        cB[3 * k + 2] = -2.0f * st * com_;
    }

    // ---- phase 1: stage input band (input rows 16q .. 16q+irows-1) ----
    const float4* src = reinterpret_cast<const float4*>(x + (size_t)b * (HW * HW)
                                                          + (size_t)(16 * q) * HW);
    float4* di = reinterpret_cast<float4*>(img);
    const int n4 = irows * (HW / 4);                // 288 or 256 float4
    for (int i = tid; i < n4; i += 256) di[i] = src[i];
    __syncthreads();

    // ---- phase 2: one patch per thread from smem ----
    if (tid < cnt) {
        int hl = tid / WO;                          // local patch row 0..7
        int wo = tid - hl * WO;
        const float* pr = img + (2 * hl) * HW + 2 * wo;

        float2 u0 = *reinterpret_cast<const float2*>(pr);
        float2 v0 = *reinterpret_cast<const float2*>(pr + 2);
        float2 u1 = *reinterpret_cast<const float2*>(pr + HW);
        float2 v1 = *reinterpret_cast<const float2*>(pr + HW + 2);
        float2 u2 = *reinterpret_cast<const float2*>(pr + 2 * HW);
        float2 v2 = *reinterpret_cast<const float2*>(pr + 2 * HW + 2);
        float2 u3 = *reinterpret_cast<const float2*>(pr + 3 * HW);
        float2 v3 = *reinterpret_cast<const float2*>(pr + 3 * HW + 2);

        float q0 = u0.x * u0.x + u0.y * u0.y + v0.x * v0.x + v0.y * v0.y;
        float q1 = u1.x * u1.x + u1.y * u1.y + v1.x * v1.x + v1.y * v1.y;
        float q2 = u2.x * u2.x + u2.y * u2.y + v2.x * v2.x + v2.y * v2.y;
        float q3 = u3.x * u3.x + u3.y * u3.y + v3.x * v3.x + v3.y * v3.y;
        float d0 = u0.x * u0.x - u0.y * u0.y - v0.x * v0.x + v0.y * v0.y;
        float d1 = u1.x * u1.x - u1.y * u1.y - v1.x * v1.x + v1.y * v1.y;
        float d2 = u2.x * u2.x - u2.y * u2.y - v2.x * v2.x + v2.y * v2.y;
        float d3 = u3.x * u3.x - u3.y * u3.y - v3.x * v3.x + v3.y * v3.y;
        float S = q0 + q1 + q2 + q3;
        float D = d0 - d1 + d2 - d3;                // row signs (+,-,+,-)
        float P = u0.x * u3.x + u0.y * u3.y + v0.x * v3.x + v0.y * v3.y
                + u1.x * u2.x + u1.y * u2.y + v1.x * v2.x + v1.y * v2.y;
        float inv = 1.0f / S;                       // reference eps cancels
        res[tid] = make_float2(D * inv, P * inv);
    }
    __syncthreads();

    // ---- phase 3: per plane, the band's cnt outputs are contiguous ----
    // 3 passes x (4 planes x 64 chunk-slots): aligned STG.128 + scalar edges.
    const size_t obase = (size_t)b * OUTB + (size_t)(8 * q) * WO;
#pragma unroll
    for (int pass = 0; pass < 3; ++pass) {
        const int p = pass * 4 + (tid >> 6);        // plane 0..11
        const int j = tid & 63;                     // chunk slot in plane
        const float a = cA[p], g = cB[p];
        const size_t gb = obase + (size_t)p * PLANE;
        int al = (int)((4 - (gb & 3)) & 3);         // head scalars to 16B align
        if (j == 0) {
            for (int e = 0; e < al; ++e) {
                float2 r = res[e];
                out[gb + e] = a * r.x + g * r.y;
            }
        }
        const int e = al + 4 * j;
        if (e + 4 <= cnt) {
            float2 r0 = res[e + 0];
            float2 r1 = res[e + 1];
            float2 r2 = res[e + 2];
            float2 r3 = res[e + 3];
            float4 o = make_float4(a * r0.x + g * r0.y, a * r1.x + g * r1.y,
                                   a * r2.x + g * r2.y, a * r3.x + g * r3.y);
            *reinterpret_cast<float4*>(out + gb + e) = o;   // 16B aligned
        }
        if (j == 63) {                              // tail scalars
            int start = al + ((cnt - al) & ~3);
            for (int e2 = start; e2 < cnt; ++e2) {
                float2 r = res[e2];
                out[gb + e2] = a * r.x + g * r.y;
            }
        }
    }
}

extern "C" void kernel_launch(void* const* d_in, const int* in_sizes, int n_in,
                              void* d_out, int out_size) {
    const float* x = (const float*)d_in[0];
    const float* w = (const float*)d_in[1];
    if (n_in >= 2 && in_sizes[0] == 48) {  // robustness: weights listed first
        x = (const float*)d_in[1];
        w = (const float*)d_in[0];
    }
    float* out = (float*)d_out;

    dim3 grd(4, BATCH, 1);   // 4 bands x 512 batches = 2048 blocks
    qconv_kernel<<<grd, 256>>>(x, w, out);
}

// round 13
// speedup vs baseline: 1.4328x; 1.4328x over previous
#include <cuda_runtime.h>
#include <math.h>

#define BATCH 512
#define HO 31
#define WO 31
#define HW 64
#define PLANE (HO * WO)

// Per-patch closed-form invariants of the quantum circuit:
//   S2 = sum p_i^2 ; D2 = signed sum (row sign (+,-,+,-), col sign (+,-,-,+))
//   dP = sum over pairs (i, i^12): rows 0<->3 and 1<->2, same column
// Outputs: per-kernel 3x2 linear map of (D2/S2, dP/S2); coefficients depend
// only on U3 of qubit 0 (wires-1..3 unitary cancels: real input, wire-0 obs).
//
// Two vertically adjacent patches per thread, ALL 12 row-loads hoisted with a
// 48-register budget (launch_bounds 128,10) so ptxas batches the LDGs (MLP=12)
// instead of interleaving load->use at 32 regs (one stall instead of ~10).

__global__ __launch_bounds__(128, 10) void qconv_kernel(const float* __restrict__ x,
                                                        const float* __restrict__ w,
                                                        float* __restrict__ out) {
    __shared__ float4 cfT[6];   // cfT[2c+0]=Dl-coef, cfT[2c+1]=dd-coef, kernels 0..3
    const int tid = threadIdx.y * 32 + threadIdx.x;
    if (tid < 4) {
        const int k = tid;
        float th = w[k * 12 + 0], ph = w[k * 12 + 1], om = w[k * 12 + 2];
        float st, ct, spo, cpo, smp, cmp, sp, cp, som, com_;
        sincosf(th, &st, &ct);
        sincosf(ph, &sp, &cp);
        sincosf(ph + om, &spo, &cpo);
        sincosf(om - ph, &smp, &cmp);
        sincosf(om, &som, &com_);
        float c2 = 0.5f * (1.0f + ct);
        float s2 = 0.5f * (1.0f - ct);
        float* cfs = reinterpret_cast<float*>(cfT);
        cfs[0 * 4 + k] = st * cp;                       // ex: Dl
        cfs[1 * 4 + k] = 2.0f * (c2 * cpo - s2 * cmp);  // ex: dd
        cfs[2 * 4 + k] = st * sp;                       // ey: Dl
        cfs[3 * 4 + k] = 2.0f * (c2 * spo + s2 * smp);  // ey: dd
        cfs[4 * 4 + k] = ct;                            // ez: Dl
        cfs[5 * 4 + k] = -2.0f * st * com_;             // ez: dd
    }
    __syncthreads();

    const int lane = threadIdx.x;
    if (lane >= WO) return;                         // keep loads in-bounds

    const int pair = blockIdx.y * 4 + threadIdx.y;  // 0..15 -> patch rows (2p,2p+1)
    const bool hasB = (pair < 15);                  // pair 15: only ho=30 valid
    const int b = blockIdx.z;

    // input rows 4*pair .. 4*pair+5 ; columns [2*lane .. 2*lane+3]
    const float* base = x + (size_t)b * (HW * HW) + (size_t)(4 * pair) * HW + lane * 2;

    // ---- all 12 loads up-front (MLP=12) ----
    float2 u0 = *reinterpret_cast<const float2*>(base);
    float2 v0 = *reinterpret_cast<const float2*>(base + 2);
    float2 u1 = *reinterpret_cast<const float2*>(base + HW);
    float2 v1 = *reinterpret_cast<const float2*>(base + HW + 2);
    float2 u2 = *reinterpret_cast<const float2*>(base + 2 * HW);
    float2 v2 = *reinterpret_cast<const float2*>(base + 2 * HW + 2);
    float2 u3 = *reinterpret_cast<const float2*>(base + 3 * HW);
    float2 v3 = *reinterpret_cast<const float2*>(base + 3 * HW + 2);
    float2 u4 = make_float2(0.f, 0.f), v4 = u4, u5 = u4, v5 = u4;
    if (hasB) {
        u4 = *reinterpret_cast<const float2*>(base + 4 * HW);
        v4 = *reinterpret_cast<const float2*>(base + 4 * HW + 2);
        u5 = *reinterpret_cast<const float2*>(base + 5 * HW);
        v5 = *reinterpret_cast<const float2*>(base + 5 * HW + 2);
    }

    // per-row invariants: s_r = |row|^2, d_r = x^2 - y^2 - z^2 + w^2
    float s0 = u0.x * u0.x + u0.y * u0.y + v0.x * v0.x + v0.y * v0.y;
    float s1 = u1.x * u1.x + u1.y * u1.y + v1.x * v1.x + v1.y * v1.y;
    float s2r = u2.x * u2.x + u2.y * u2.y + v2.x * v2.x + v2.y * v2.y;
    float s3 = u3.x * u3.x + u3.y * u3.y + v3.x * v3.x + v3.y * v3.y;
    float d0 = u0.x * u0.x - u0.y * u0.y - v0.x * v0.x + v0.y * v0.y;
    float d1 = u1.x * u1.x - u1.y * u1.y - v1.x * v1.x + v1.y * v1.y;
    float d2 = u2.x * u2.x - u2.y * u2.y - v2.x * v2.x + v2.y * v2.y;
    float d3 = u3.x * u3.x - u3.y * u3.y - v3.x * v3.x + v3.y * v3.y;

    // ---- patch A: rows 0..3 ----
    float SA = s0 + s1 + s2r + s3;
    float DA = d0 - d1 + d2 - d3;
    float PA = u0.x * u3.x + u0.y * u3.y + v0.x * v3.x + v0.y * v3.y
             + u1.x * u2.x + u1.y * u2.y + v1.x * v2.x + v1.y * v2.y;
    float invA = 1.0f / SA;
    float DlA = DA * invA, ddA = PA * invA;

    // ---- patch B: rows 2..5 ----
    float DlB = 0.f, ddB = 0.f;
    if (hasB) {
        float s4 = u4.x * u4.x + u4.y * u4.y + v4.x * v4.x + v4.y * v4.y;
        float s5 = u5.x * u5.x + u5.y * u5.y + v5.x * v5.x + v5.y * v5.y;
        float d4 = u4.x * u4.x - u4.y * u4.y - v4.x * v4.x + v4.y * v4.y;
        float d5 = u5.x * u5.x - u5.y * u5.y - v5.x * v5.x + v5.y * v5.y;
        float SB = s2r + s3 + s4 + s5;
        float DB = d2 - d3 + d4 - d5;
        float PB = u2.x * u5.x + u2.y * u5.y + v2.x * v5.x + v2.y * v5.y
                 + u3.x * u4.x + u3.y * u4.y + v3.x * v4.x + v3.y * v4.y;
        float invB = 1.0f / SB;
        DlB = DB * invB;
        ddB = PB * invB;
    }

    // ---- epilogue: 24 stores (12 per patch) ----
    const size_t obase = (size_t)b * 12 * PLANE + (size_t)(2 * pair) * WO + lane;
#pragma unroll
    for (int c = 0; c < 3; ++c) {
        float4 a = cfT[2 * c + 0];
        float4 g = cfT[2 * c + 1];
        out[obase + (size_t)(0 + c) * PLANE] = a.x * DlA + g.x * ddA;
        out[obase + (size_t)(3 + c) * PLANE] = a.y * DlA + g.y * ddA;
        out[obase + (size_t)(6 + c) * PLANE] = a.z * DlA + g.z * ddA;
        out[obase + (size_t)(9 + c) * PLANE] = a.w * DlA + g.w * ddA;
        if (hasB) {
            out[obase + WO + (size_t)(0 + c) * PLANE] = a.x * DlB + g.x * ddB;
            out[obase + WO + (size_t)(3 + c) * PLANE] = a.y * DlB + g.y * ddB;
            out[obase + WO + (size_t)(6 + c) * PLANE] = a.z * DlB + g.z * ddB;
            out[obase + WO + (size_t)(9 + c) * PLANE] = a.w * DlB + g.w * ddB;
        }
    }
}

extern "C" void kernel_launch(void* const* d_in, const int* in_sizes, int n_in,
                              void* d_out, int out_size) {
    const float* x = (const float*)d_in[0];
    const float* w = (const float*)d_in[1];
    if (n_in >= 2 && in_sizes[0] == 48) {  // robustness: weights listed first
        x = (const float*)d_in[1];
        w = (const float*)d_in[0];
    }
    float* out = (float*)d_out;

    dim3 blk(32, 4, 1);
    dim3 grd(1, 4, BATCH);   // 4 y-blocks x 4 pairs = 16 pairs cover HO=31
    qconv_kernel<<<grd, blk>>>(x, w, out);
}